// round 9
// baseline (speedup 1.0000x reference)
#include <cuda_runtime.h>
#include <cuda_fp16.h>
#include <mma.h>
#include <cstdint>

using namespace nvcuda;

// ======================= problem constants =======================
#define C_DIM 128
#define MAX_K 512
#define BM 128
#define BN 256
#define EPS 1e-8f
#define NTHREADS 512

// ======================= smem layout (bytes) =======================
#define LDA_RAW 132                 // fp32 A staging row stride (floats)
#define LDH     136                 // fp16 tile row stride (halves)
#define SM_A_RAW 0                                   // 128*132*4 = 67584
#define SM_AH0   (128 * LDA_RAW * 4)                 // 67584 (+34816)
#define SM_AH1   (SM_AH0 + 128 * LDH * 2)            // 102400 (+34816)
#define SM_B     (SM_AH1 + 128 * LDH * 2)            // 137216 (+69632)
#define SMEM_TOTAL (SM_B + 256 * LDH * 2)            // 206848

// Scratch: normalized prototypes as fp16. 128 KB.
__device__ __half g_protoH[MAX_K * C_DIM];

// ======================= helpers =======================
__device__ __forceinline__ uint32_t s2u(const void* p) {
    uint32_t a;
    asm("{ .reg .u64 t; cvta.to.shared.u64 t, %1; cvt.u32.u64 %0, t; }" : "=r"(a) : "l"(p));
    return a;
}
__device__ __forceinline__ void cp_async16(uint32_t dst, const void* src) {
    asm volatile("cp.async.cg.shared.global [%0], [%1], 16;" :: "r"(dst), "l"(src));
}
#define CP_COMMIT() asm volatile("cp.async.commit_group;" ::: "memory")
#define CP_WAIT0()  asm volatile("cp.async.wait_group 0;"  ::: "memory")

__device__ __forceinline__ uint32_t h2u(__half2 h) {
    return *reinterpret_cast<uint32_t*>(&h);
}

// ======================= kernel 1: proto normalize -> fp16 =======================
__global__ void proto_norm_kernel(const float* __restrict__ P, int K) {
    int warp = (blockIdx.x * blockDim.x + threadIdx.x) >> 5;
    int lane = threadIdx.x & 31;
    if (warp >= K) return;
    const float4* row = reinterpret_cast<const float4*>(P + (size_t)warp * C_DIM);
    float4 v = row[lane];
    float s = v.x * v.x + v.y * v.y + v.z * v.z + v.w * v.w;
#pragma unroll
    for (int o = 16; o; o >>= 1) s += __shfl_xor_sync(0xFFFFFFFFu, s, o);
    float inv = 1.0f / fmaxf(sqrtf(s), EPS);
    __half2 h0 = __floats2half2_rn(v.x * inv, v.y * inv);
    __half2 h1 = __floats2half2_rn(v.z * inv, v.w * inv);
    reinterpret_cast<__half2*>(g_protoH + (size_t)warp * C_DIM)[lane * 2 + 0] = h0;
    reinterpret_cast<__half2*>(g_protoH + (size_t)warp * C_DIM)[lane * 2 + 1] = h1;
}

// ======================= kernel 2: persistent pipelined fp16 GEMM, 16 warps ===========
__global__ __launch_bounds__(NTHREADS, 1)
void hsproto_gemm_kernel(const float* __restrict__ E, float* __restrict__ out,
                         int nRowTiles, int Kout) {
    extern __shared__ char smem[];
    const uint32_t sb = s2u(smem);
    float*  A_raw = reinterpret_cast<float*>(smem + SM_A_RAW);
    __half* B_h   = reinterpret_cast<__half*>(smem + SM_B);

    const int tid = threadIdx.x;
    const int colBase = blockIdx.x * BN;
    const int STRIDE = gridDim.y;

    // A ownership: quarter-row per thread. Row r = tid>>2, quarter q = tid&3 (32 floats).
    const int r = tid >> 2;
    const int q = tid & 3;
    const float* myRaw = A_raw + r * LDA_RAW + q * 32;
    const uint32_t aRawDst = sb + SM_A_RAW + (uint32_t)(r * LDA_RAW + q * 32) * 4;

    // ---- prologue: B tile (half-row per thread) + first A tile ----
    {
        const int rb = tid >> 1, hb = tid & 1;
        const __half* gB = g_protoH + (size_t)(colBase + rb) * C_DIM + hb * 64;
        uint32_t bDst = sb + SM_B + (uint32_t)(rb * LDH + hb * 64) * 2;
#pragma unroll
        for (int j = 0; j < 8; j++) cp_async16(bDst + j * 16, gB + j * 8);

        const float* gA = E + ((size_t)blockIdx.y * BM + r) * C_DIM + q * 32;
#pragma unroll
        for (int j = 0; j < 8; j++) cp_async16(aRawDst + j * 16, gA + j * 4);
        CP_COMMIT();
        CP_WAIT0();
    }

    // convert(first) -> A_h buffer 0 (row-sum via 2 shfls within the lane quad)
    {
        float s = 0.0f;
#pragma unroll
        for (int j = 0; j < 8; j++) {
            float4 v = reinterpret_cast<const float4*>(myRaw)[j];
            s += v.x * v.x + v.y * v.y + v.z * v.z + v.w * v.w;
        }
        s += __shfl_xor_sync(0xFFFFFFFFu, s, 1);
        s += __shfl_xor_sync(0xFFFFFFFFu, s, 2);
        float inv = 1.0f / fmaxf(sqrtf(s), EPS);
        __half* myH = reinterpret_cast<__half*>(smem + SM_AH0) + r * LDH + q * 32;
#pragma unroll
        for (int j = 0; j < 4; j++) {
            float4 v0 = reinterpret_cast<const float4*>(myRaw)[j * 2 + 0];
            float4 v1 = reinterpret_cast<const float4*>(myRaw)[j * 2 + 1];
            uint4 pk;
            pk.x = h2u(__floats2half2_rn(v0.x * inv, v0.y * inv));
            pk.y = h2u(__floats2half2_rn(v0.z * inv, v0.w * inv));
            pk.z = h2u(__floats2half2_rn(v1.x * inv, v1.y * inv));
            pk.w = h2u(__floats2half2_rn(v1.z * inv, v1.w * inv));
            reinterpret_cast<uint4*>(myH)[j] = pk;
        }
    }

    // MMA warp layout: 16 warps; warp tile 32x64. wm: 0..3 (rows), wn: 0..3 (cols).
    const int warpId = tid >> 5;
    const int wm = warpId >> 2;
    const int wn = warpId & 3;
    int buf = 0;

    for (int rt = blockIdx.y; rt < nRowTiles; rt += STRIDE) {
        __syncthreads();   // A_h[buf] STS visible; prev converts done -> A_raw WAR-safe

        const bool hasNext = (rt + STRIDE) < nRowTiles;
        if (hasNext) {
            const float* gA = E + ((size_t)(rt + STRIDE) * BM + r) * C_DIM + q * 32;
#pragma unroll
            for (int j = 0; j < 8; j++) cp_async16(aRawDst + j * 16, gA + j * 4);
            CP_COMMIT();
        }

        const __half* A_h = reinterpret_cast<const __half*>(smem + (buf ? SM_AH1 : SM_AH0));

        // ---- fp16 MMA: warp tile 32x64 = 2x4 m16n16k16 fragments ----
        wmma::fragment<wmma::accumulator, 16, 16, 16, float> acc[2][4];
#pragma unroll
        for (int i = 0; i < 2; i++)
#pragma unroll
            for (int j = 0; j < 4; j++) wmma::fill_fragment(acc[i][j], 0.0f);

#pragma unroll
        for (int kk = 0; kk < C_DIM; kk += 16) {
            wmma::fragment<wmma::matrix_a, 16, 16, 16, __half, wmma::row_major> a[2];
            wmma::fragment<wmma::matrix_b, 16, 16, 16, __half, wmma::col_major> b[4];
#pragma unroll
            for (int i = 0; i < 2; i++)
                wmma::load_matrix_sync(a[i], A_h + (wm * 32 + i * 16) * LDH + kk, LDH);
#pragma unroll
            for (int j = 0; j < 4; j++)
                wmma::load_matrix_sync(b[j], B_h + (wn * 64 + j * 16) * LDH + kk, LDH);
#pragma unroll
            for (int i = 0; i < 2; i++)
#pragma unroll
                for (int j = 0; j < 4; j++)
                    wmma::mma_sync(acc[i][j], a[i], b[j], acc[i][j]);
        }

        // ---- convert(t+1): drains while HMMAs complete (no acc dependence) ----
        if (hasNext) {
            CP_WAIT0();
            float s = 0.0f;
#pragma unroll
            for (int j = 0; j < 8; j++) {
                float4 v = reinterpret_cast<const float4*>(myRaw)[j];
                s += v.x * v.x + v.y * v.y + v.z * v.z + v.w * v.w;
            }
            s += __shfl_xor_sync(0xFFFFFFFFu, s, 1);
            s += __shfl_xor_sync(0xFFFFFFFFu, s, 2);
            float inv = 1.0f / fmaxf(sqrtf(s), EPS);
            __half* myH = reinterpret_cast<__half*>(smem + (buf ? SM_AH0 : SM_AH1))
                          + r * LDH + q * 32;
#pragma unroll
            for (int j = 0; j < 4; j++) {
                float4 v0 = reinterpret_cast<const float4*>(myRaw)[j * 2 + 0];
                float4 v1 = reinterpret_cast<const float4*>(myRaw)[j * 2 + 1];
                uint4 pk;
                pk.x = h2u(__floats2half2_rn(v0.x * inv, v0.y * inv));
                pk.y = h2u(__floats2half2_rn(v0.z * inv, v0.w * inv));
                pk.z = h2u(__floats2half2_rn(v1.x * inv, v1.y * inv));
                pk.w = h2u(__floats2half2_rn(v1.z * inv, v1.w * inv));
                reinterpret_cast<uint4*>(myH)[j] = pk;
            }
        }

        // ---- epilogue(t): -(1-cos)^2, store (waits on HMMA scoreboard) ----
        float* outBase = out + ((size_t)rt * BM) * Kout + colBase;
#pragma unroll
        for (int i = 0; i < 2; i++) {
#pragma unroll
            for (int j = 0; j < 4; j++) {
#pragma unroll
                for (int e = 0; e < acc[i][j].num_elements; e++) {
                    float d = 1.0f - acc[i][j].x[e];
                    acc[i][j].x[e] = -(d * d);
                }
                wmma::store_matrix_sync(outBase + (size_t)(wm * 32 + i * 16) * Kout
                                                + (wn * 64 + j * 16),
                                        acc[i][j], Kout, wmma::mem_row_major);
            }
        }

        buf ^= 1;
    }
}

// ======================= launcher =======================
extern "C" void kernel_launch(void* const* d_in, const int* in_sizes, int n_in,
                              void* d_out, int out_size) {
    const float* E = (const float*)d_in[0];
    const float* P = (const float*)d_in[1];
    float* out = (float*)d_out;

    const int N = in_sizes[0] / C_DIM;   // 131072
    const int K = in_sizes[1] / C_DIM;   // 512

    proto_norm_kernel<<<(K * 32 + 255) / 256, 256>>>(P, K);

    static int sms = 0;
    if (!sms) {
        cudaDeviceGetAttribute(&sms, cudaDevAttrMultiProcessorCount, 0);
        cudaFuncSetAttribute(hsproto_gemm_kernel,
                             cudaFuncAttributeMaxDynamicSharedMemorySize, SMEM_TOTAL);
    }
    const int nColTiles = K / BN;                 // 2
    int stripe = sms / nColTiles;                 // persistent CTAs per column
    if (stripe < 1) stripe = 1;
    const int nRowTiles = N / BM;                 // 1024
    if (stripe > nRowTiles) stripe = nRowTiles;

    dim3 grid(nColTiles, stripe);
    hsproto_gemm_kernel<<<grid, NTHREADS, SMEM_TOTAL>>>(E, out, nRowTiles, K);
}

// round 10
// speedup vs baseline: 1.1525x; 1.1525x over previous
#include <cuda_runtime.h>
#include <cuda_fp16.h>
#include <mma.h>
#include <cstdint>

using namespace nvcuda;

// ======================= problem constants =======================
#define C_DIM 128
#define MAX_K 512
#define BM 64                 // rows per warp-group tile
#define BN 256
#define EPS 1e-8f
#define NTHREADS 512

#define LDH     136           // fp16 tile row stride (halves)
#define LDS_SCR 260           // epilogue scratch row stride (floats)

// ---- smem layout (bytes) ----
// B:          256*136*2 = 69632            @ 0
// A_h[g]:      64*136*2 = 17408 each       @ 69632 + g*17408
// scratch[g]:  32*260*4 = 33280 (pad 33536) @ 104448 + g*33536
#define SM_B        0
#define SM_AH(g)    (69632 + (g) * 17408)
#define SM_SCR(g)   (104448 + (g) * 33536)
#define SMEM_TOTAL  (104448 + 2 * 33536)    // 171520

// Scratch: normalized prototypes as fp16. 128 KB.
__device__ __half g_protoH[MAX_K * C_DIM];

// ======================= helpers =======================
__device__ __forceinline__ uint32_t s2u(const void* p) {
    uint32_t a;
    asm("{ .reg .u64 t; cvta.to.shared.u64 t, %1; cvt.u32.u64 %0, t; }" : "=r"(a) : "l"(p));
    return a;
}
__device__ __forceinline__ void cp_async16(uint32_t dst, const void* src) {
    asm volatile("cp.async.cg.shared.global [%0], [%1], 16;" :: "r"(dst), "l"(src));
}
#define CP_COMMIT() asm volatile("cp.async.commit_group;" ::: "memory")
#define CP_WAIT0()  asm volatile("cp.async.wait_group 0;"  ::: "memory")
#define BAR_G(id)   asm volatile("bar.sync %0, 256;" :: "r"(id) : "memory")

__device__ __forceinline__ uint32_t h2u(__half2 h) {
    return *reinterpret_cast<uint32_t*>(&h);
}

// ======================= kernel 1: proto normalize -> fp16 =======================
__global__ void proto_norm_kernel(const float* __restrict__ P, int K) {
    int warp = (blockIdx.x * blockDim.x + threadIdx.x) >> 5;
    int lane = threadIdx.x & 31;
    if (warp >= K) return;
    const float4* row = reinterpret_cast<const float4*>(P + (size_t)warp * C_DIM);
    float4 v = row[lane];
    float s = v.x * v.x + v.y * v.y + v.z * v.z + v.w * v.w;
#pragma unroll
    for (int o = 16; o; o >>= 1) s += __shfl_xor_sync(0xFFFFFFFFu, s, o);
    float inv = 1.0f / fmaxf(sqrtf(s), EPS);
    __half2 h0 = __floats2half2_rn(v.x * inv, v.y * inv);
    __half2 h1 = __floats2half2_rn(v.z * inv, v.w * inv);
    reinterpret_cast<__half2*>(g_protoH + (size_t)warp * C_DIM)[lane * 2 + 0] = h0;
    reinterpret_cast<__half2*>(g_protoH + (size_t)warp * C_DIM)[lane * 2 + 1] = h1;
}

// ======================= kernel 2: dual warp-group pipelined fp16 GEMM ============
// Two independent 8-warp groups per CTA (named barriers), shared B tile.
// Per group-iter t: MMA(t) -> bar -> STS conv(t+1) -> LDG raw(t+2) ->
//                   staged epilogue(t) (covers LDG) -> reduce+pack(t+2).
__global__ __launch_bounds__(NTHREADS, 1)
void hsproto_gemm_kernel(const float* __restrict__ E, float* __restrict__ out,
                         int nRowTiles, int Kout) {
    extern __shared__ char smem[];
    __half* B_h = reinterpret_cast<__half*>(smem + SM_B);

    const int tid = threadIdx.x;
    const int g   = tid >> 8;                  // warp-group 0/1
    const int gt  = tid & 255;                 // thread within group
    const int lane = tid & 31;
    const int colBase = blockIdx.x * BN;
    const int barid = g + 1;

    __half* A_h     = reinterpret_cast<__half*>(smem + SM_AH(g));
    float*  scratch = reinterpret_cast<float*>(smem + SM_SCR(g));

    // ---- prologue: B tile via cp.async (all 512 threads) ----
    {
        const int rb = tid >> 1, hb = tid & 1;
        const __half* gB = g_protoH + (size_t)(colBase + rb) * C_DIM + hb * 64;
        uint32_t bDst = s2u(smem) + SM_B + (uint32_t)(rb * LDH + hb * 64) * 2;
#pragma unroll
        for (int j = 0; j < 8; j++) cp_async16(bDst + j * 16, gB + j * 8);
        CP_COMMIT();
    }

    // A staging: warp-local. Warp w owns rows [w*8, w*8+8); lane l owns float4 col l.
    const int w  = gt >> 5;                    // warp within group: 0..7
    const int rowBaseW = w * 8;                // tile-local first row of this warp
    const int step = gridDim.y * 2;            // row-tile stride across all groups
    int rt = blockIdx.y * 2 + g;               // first row tile for this group

    float4  raw[8];                            // one float4 per row j
    uint32_t pk[16];                           // fp16x2-packed normalized tile slice

    // LDG: contiguous 512B per warp-instr (row j), lane l -> float4 l
    auto LDG_TILE = [&](int t) {
#pragma unroll
        for (int j = 0; j < 8; j++) {
            const float4* gA = reinterpret_cast<const float4*>(
                E + ((size_t)t * BM + rowBaseW + j) * C_DIM);
            raw[j] = gA[lane];
        }
    };
    // norms: per-row sumsq allreduced across the warp; pack scaled fp16 pairs
    auto REDUCE_PACK = [&]() {
        float s[8];
#pragma unroll
        for (int j = 0; j < 8; j++)
            s[j] = raw[j].x * raw[j].x + raw[j].y * raw[j].y +
                   raw[j].z * raw[j].z + raw[j].w * raw[j].w;
#pragma unroll
        for (int o = 16; o; o >>= 1)
#pragma unroll
            for (int j = 0; j < 8; j++) s[j] += __shfl_xor_sync(0xFFFFFFFFu, s[j], o);
#pragma unroll
        for (int j = 0; j < 8; j++) {
            float inv = 1.0f / fmaxf(sqrtf(s[j]), EPS);
            pk[j * 2 + 0] = h2u(__floats2half2_rn(raw[j].x * inv, raw[j].y * inv));
            pk[j * 2 + 1] = h2u(__floats2half2_rn(raw[j].z * inv, raw[j].w * inv));
        }
    };
    // STS packed tile slice: row rowBaseW+j, 8 bytes at half-col lane*4
    auto STS_TILE = [&]() {
#pragma unroll
        for (int j = 0; j < 8; j++) {
            uint2 v; v.x = pk[j * 2]; v.y = pk[j * 2 + 1];
            *reinterpret_cast<uint2*>(A_h + (rowBaseW + j) * LDH + lane * 4) = v;
        }
    };

    // prologue per group: conv(t0) -> A_h; prepare packed(t1)
    LDG_TILE(rt);
    REDUCE_PACK();
    STS_TILE();
    if (rt + step < nRowTiles) { LDG_TILE(rt + step); REDUCE_PACK(); }

    CP_WAIT0();
    __syncthreads();                           // B + first A_h visible everywhere

    const int wm = w >> 2;                     // 0..1 : 32-row band
    const int wn = w & 3;                      // 0..3 : 64-col band
    const int f4 = gt & 63;                    // epilogue STG: float4 col
    const int sr0 = gt >> 6;                   // epilogue STG: row offset 0..3

    for (int t = rt; t < nRowTiles; t += step) {
        // ---- 1. MMA(t): warp tile 32x64 = 2x4 m16n16k16 ----
        wmma::fragment<wmma::accumulator, 16, 16, 16, float> acc[2][4];
#pragma unroll
        for (int i = 0; i < 2; i++)
#pragma unroll
            for (int j = 0; j < 4; j++) wmma::fill_fragment(acc[i][j], 0.0f);

#pragma unroll
        for (int kk = 0; kk < C_DIM; kk += 16) {
            wmma::fragment<wmma::matrix_a, 16, 16, 16, __half, wmma::row_major> a[2];
            wmma::fragment<wmma::matrix_b, 16, 16, 16, __half, wmma::col_major> b[4];
#pragma unroll
            for (int i = 0; i < 2; i++)
                wmma::load_matrix_sync(a[i], A_h + (wm * 32 + i * 16) * LDH + kk, LDH);
#pragma unroll
            for (int j = 0; j < 4; j++)
                wmma::load_matrix_sync(b[j], B_h + (wn * 64 + j * 16) * LDH + kk, LDH);
#pragma unroll
            for (int i = 0; i < 2; i++)
#pragma unroll
                for (int j = 0; j < 4; j++)
                    wmma::mma_sync(acc[i][j], a[i], b[j], acc[i][j]);
        }

        // ---- 2. group barrier: all MMA(t) smem reads done -> A_h overwritable ----
        BAR_G(barid);

        const bool has1 = (t + step) < nRowTiles;
        const bool has2 = (t + 2 * step) < nRowTiles;

        // ---- 3. STS conv(t+1); issue LDG raw(t+2) (latency hidden by epilogue) ----
        if (has1) STS_TILE();
        if (has2) LDG_TILE(t + 2 * step);

        // ---- 4. staged epilogue(t): -(1-cos)^2, coalesced STG.128 ----
        float* outBase = out + ((size_t)t * BM) * Kout + colBase;
#pragma unroll
        for (int p = 0; p < 2; p++) {
            if (wm == p) {
#pragma unroll
                for (int i = 0; i < 2; i++)
#pragma unroll
                    for (int j = 0; j < 4; j++) {
#pragma unroll
                        for (int e = 0; e < acc[i][j].num_elements; e++) {
                            float d = 1.0f - acc[i][j].x[e];
                            acc[i][j].x[e] = -(d * d);
                        }
                        wmma::store_matrix_sync(scratch + (i * 16) * LDS_SCR + wn * 64 + j * 16,
                                                acc[i][j], LDS_SCR, wmma::mem_row_major);
                    }
            }
            BAR_G(barid);
#pragma unroll
            for (int j = 0; j < 8; j++) {
                int srow = sr0 + j * 4;
                float4 v = *reinterpret_cast<const float4*>(scratch + srow * LDS_SCR + f4 * 4);
                *reinterpret_cast<float4*>(outBase + (size_t)(p * 32 + srow) * Kout + f4 * 4) = v;
            }
            BAR_G(barid);
        }

        // ---- 5. reduce+pack(t+2): stalls only if LDG outlived the epilogue ----
        if (has2) REDUCE_PACK();
    }
}

// ======================= launcher =======================
extern "C" void kernel_launch(void* const* d_in, const int* in_sizes, int n_in,
                              void* d_out, int out_size) {
    const float* E = (const float*)d_in[0];
    const float* P = (const float*)d_in[1];
    float* out = (float*)d_out;

    const int N = in_sizes[0] / C_DIM;   // 131072
    const int K = in_sizes[1] / C_DIM;   // 512

    proto_norm_kernel<<<(K * 32 + 255) / 256, 256>>>(P, K);

    static int sms = 0;
    if (!sms) {
        cudaDeviceGetAttribute(&sms, cudaDevAttrMultiProcessorCount, 0);
        cudaFuncSetAttribute(hsproto_gemm_kernel,
                             cudaFuncAttributeMaxDynamicSharedMemorySize, SMEM_TOTAL);
    }
    const int nColTiles = K / BN;                 // 2
    int stripe = sms / nColTiles;                 // persistent CTAs per column (76)
    if (stripe < 1) stripe = 1;
    const int nRowTiles = N / BM;                 // 2048

    dim3 grid(nColTiles, stripe);
    hsproto_gemm_kernel<<<grid, NTHREADS, SMEM_TOTAL>>>(E, out, nRowTiles, K);
}